// round 6
// baseline (speedup 1.0000x reference)
#include <cuda_runtime.h>

#define BATCH 16384
#define STEPS 200
#define LR 0.01f
#define HID 64
#define PROJ 8
#define SPEC 40
#define TPB 256

typedef unsigned long long ull;

// Precomputed A = (W2 @ R^T) @ R[:, :6]  -> [HID][6]
__device__ float g_A[HID * 6];

// ---------------------------------------------------------------------------
// Prologue: A[k][i] = sum_p ( sum_j W2[k,j]*R[p,j] ) * R[p,i]
// ---------------------------------------------------------------------------
__global__ void compute_A_kernel(const float* __restrict__ W2,
                                 const float* __restrict__ R) {
    int k = threadIdx.x;
    if (k >= HID) return;
    float wr[PROJ];
#pragma unroll
    for (int p = 0; p < PROJ; p++) {
        float s = 0.f;
#pragma unroll
        for (int j = 0; j < SPEC; j++)
            s = fmaf(W2[k * SPEC + j], R[p * SPEC + j], s);
        wr[p] = s;
    }
#pragma unroll
    for (int i = 0; i < 6; i++) {
        float s = 0.f;
#pragma unroll
        for (int p = 0; p < PROJ; p++)
            s = fmaf(wr[p], R[p * SPEC + i], s);
        g_A[k * 6 + i] = s;
    }
}

// ---- packed f32x2 helpers --------------------------------------------------
__device__ __forceinline__ ull fma2(ull a, ull b, ull c) {
    ull r;
    asm("fma.rn.f32x2 %0, %1, %2, %3;" : "=l"(r) : "l"(a), "l"(b), "l"(c));
    return r;
}
__device__ __forceinline__ ull pk(float lo, float hi) {
    ull r;
    asm("mov.b64 %0, {%1, %2};" : "=l"(r) : "f"(lo), "f"(hi));
    return r;
}
__device__ __forceinline__ void upk(ull v, float& lo, float& hi) {
    asm("mov.b64 {%0, %1}, %2;" : "=f"(lo), "=f"(hi) : "l"(v));
}
__device__ __forceinline__ ull pkc(float lo, float hi) {  // non-asm (fill path)
    return (ull)__float_as_uint(lo) | ((ull)__float_as_uint(hi) << 32);
}
// accurate tanh: 1 - 2/(exp(2x)+1); exp via MUFU.EX2, div via MUFU.RCP
// (~1e-7 abs err; same path as the R3 kernel that measured rel_err 1.7e-7)
__device__ __forceinline__ float tanh_acc(float x) {
    float e;
    asm("ex2.approx.f32 %0, %1;" : "=f"(e) : "f"(2.885390081777927f * x));
    float r;
    asm("rcp.approx.f32 %0, %1;" : "=f"(r) : "f"(e + 1.f));
    return fmaf(-2.f, r, 1.f);
}

// ---------------------------------------------------------------------------
// Solver: TWO threads per row (split-K over the 64 hidden units, 32 each),
// hidden units processed as packed (k,k+1) pairs with fma.rn.f32x2.
//
// Shared layout: 32 pair-blocks, block index q = p*2 + half  (p = 0..15 within
// a thread, half = thread's split-K side). Each block = 7 ulonglong2:
//   u2[0] = {W1[0][k0,k1], W1[1][k0,k1]}   (each element is a packed f32x2)
//   u2[1] = {W1[2][..],    W1[3][..]}
//   u2[2] = {W1[4][..],    W1[5][..]}
//   u2[3] = {b1[..],       A0[..]}
//   u2[4] = {A1, A2}   u2[5] = {A3, A4}   u2[6] = {A5, pad}
// where k0 = half*32 + p*2, k1 = k0+1.
// Consumer address (ulonglong2 units):  sWA + (p*2 + half)*7  =  wbase + p*14
// with wbase = sWA + half*7.            <-- R4's bug was `+ p*7` here.
// ---------------------------------------------------------------------------
__global__ __launch_bounds__(TPB, 1)
void solve_kernel(const float* __restrict__ spec,
                  const float* __restrict__ W1,
                  const float* __restrict__ b1,
                  const float* __restrict__ b2,
                  const float* __restrict__ R,
                  float* __restrict__ out) {
    __shared__ ulonglong2 sWA[32 * 7];       // 3584 B
    __shared__ float sR[PROJ * SPEC];
    __shared__ float sB2[SPEC];

    const int tid = threadIdx.x;

    if (tid < 32) {
        const int half = tid & 1, p = tid >> 1;
        const int k0 = half * 32 + p * 2, k1 = k0 + 1;
        ull* b = (ull*)(sWA + tid * 7);      // block q = tid = p*2 + half
#pragma unroll
        for (int i = 0; i < 6; i++)
            b[i] = pkc(W1[i * HID + k0], W1[i * HID + k1]);
        b[6] = pkc(b1[k0], b1[k1]);
#pragma unroll
        for (int j = 0; j < 6; j++)
            b[7 + j] = pkc(g_A[k0 * 6 + j], g_A[k1 * 6 + j]);
        b[13] = 0ULL;
    }
    for (int idx = tid; idx < PROJ * SPEC; idx += TPB) sR[idx] = R[idx];
    if (tid < SPEC) sB2[tid] = b2[tid];
    __syncthreads();

    const int gt   = blockIdx.x * TPB + tid;   // 0 .. 32767
    const int row  = gt >> 1;
    const int half = gt & 1;
    const ulonglong2* wbase = sWA + half * 7;

    // Per-row constant: c = R[:, :6]^T @ ( R @ (b2 - spec_row) )
    float z[PROJ];
#pragma unroll
    for (int p = 0; p < PROJ; p++) z[p] = 0.f;
    const float* srow = spec + (size_t)row * SPEC;
#pragma unroll 8
    for (int j = 0; j < SPEC; j++) {
        float d = sB2[j] - srow[j];
#pragma unroll
        for (int p = 0; p < PROJ; p++)
            z[p] = fmaf(sR[p * SPEC + j], d, z[p]);
    }
    float c0 = 0.f, c1 = 0.f, c2 = 0.f, c3 = 0.f, c4 = 0.f, c5 = 0.f;
#pragma unroll
    for (int p = 0; p < PROJ; p++) {
        c0 = fmaf(sR[p * SPEC + 0], z[p], c0);
        c1 = fmaf(sR[p * SPEC + 1], z[p], c1);
        c2 = fmaf(sR[p * SPEC + 2], z[p], c2);
        c3 = fmaf(sR[p * SPEC + 3], z[p], c3);
        c4 = fmaf(sR[p * SPEC + 4], z[p], c4);
        c5 = fmaf(sR[p * SPEC + 5], z[p], c5);
    }

    float u0 = 0.5f, u1 = 0.5f, u2 = 0.5f, u3 = 0.5f, u4 = 0.5f, u5 = 0.5f;

    for (int t = 0; t < STEPS; t++) {
        const ull pu0 = pk(u0, u0), pu1 = pk(u1, u1), pu2 = pk(u2, u2),
                  pu3 = pk(u3, u3), pu4 = pk(u4, u4), pu5 = pk(u5, u5);
        ull G0 = 0ULL, G1 = 0ULL, G2 = 0ULL, G3 = 0ULL, G4 = 0ULL, G5 = 0ULL;
#pragma unroll
        for (int p = 0; p < 16; p++) {
            const ulonglong2* wb = wbase + p * 14;   // block q = p*2 + half
            const ulonglong2 v0 = wb[0];   // {Wi0, Wi1}
            const ulonglong2 v1 = wb[1];   // {Wi2, Wi3}
            const ulonglong2 v2 = wb[2];   // {Wi4, Wi5}
            const ulonglong2 v3 = wb[3];   // {b,   a0}
            ull pre2 = v3.x;
            pre2 = fma2(pu0, v0.x, pre2);
            pre2 = fma2(pu1, v0.y, pre2);
            pre2 = fma2(pu2, v1.x, pre2);
            pre2 = fma2(pu3, v1.y, pre2);
            pre2 = fma2(pu4, v2.x, pre2);
            pre2 = fma2(pu5, v2.y, pre2);
            float x0, x1;
            upk(pre2, x0, x1);
            const float h0 = tanh_acc(x0);
            const float h1 = tanh_acc(x1);
            const ull h2 = pk(h0, h1);
            const ulonglong2 v4 = wb[4];   // {a1, a2}
            const ulonglong2 v5 = wb[5];   // {a3, a4}
            const ulonglong2 v6 = wb[6];   // {a5, pad}
            G0 = fma2(h2, v3.y, G0);
            G1 = fma2(h2, v4.x, G1);
            G2 = fma2(h2, v4.y, G2);
            G3 = fma2(h2, v5.x, G3);
            G4 = fma2(h2, v5.y, G4);
            G5 = fma2(h2, v6.x, G5);
        }
        // fold packed lanes, then reduce across the 2 split-K threads
        float a, b;
        float g0, g1, g2, g3, g4, g5;
        upk(G0, a, b); g0 = a + b;
        upk(G1, a, b); g1 = a + b;
        upk(G2, a, b); g2 = a + b;
        upk(G3, a, b); g3 = a + b;
        upk(G4, a, b); g4 = a + b;
        upk(G5, a, b); g5 = a + b;
        g0 += __shfl_xor_sync(0xffffffffu, g0, 1);
        g1 += __shfl_xor_sync(0xffffffffu, g1, 1);
        g2 += __shfl_xor_sync(0xffffffffu, g2, 1);
        g3 += __shfl_xor_sync(0xffffffffu, g3, 1);
        g4 += __shfl_xor_sync(0xffffffffu, g4, 1);
        g5 += __shfl_xor_sync(0xffffffffu, g5, 1);
        // u = clip(u - LR*(g + c), 0, 1)
        u0 = fminf(fmaxf(fmaf(-LR, g0, fmaf(-LR, c0, u0)), 0.f), 1.f);
        u1 = fminf(fmaxf(fmaf(-LR, g1, fmaf(-LR, c1, u1)), 0.f), 1.f);
        u2 = fminf(fmaxf(fmaf(-LR, g2, fmaf(-LR, c2, u2)), 0.f), 1.f);
        u3 = fminf(fmaxf(fmaf(-LR, g3, fmaf(-LR, c3, u3)), 0.f), 1.f);
        u4 = fminf(fmaxf(fmaf(-LR, g4, fmaf(-LR, c4, u4)), 0.f), 1.f);
        u5 = fminf(fmaxf(fmaf(-LR, g5, fmaf(-LR, c5, u5)), 0.f), 1.f);
    }

    if (half == 0) {
        float* orow = out + (size_t)row * 6;
        orow[0] = u0; orow[1] = u1; orow[2] = u2;
        orow[3] = u3; orow[4] = u4; orow[5] = u5;
    }
}

// ---------------------------------------------------------------------------
// Inputs (metadata order): spectrum, W1, b1, W2, b2, R.  Output: (BATCH, 6) f32
// ---------------------------------------------------------------------------
extern "C" void kernel_launch(void* const* d_in, const int* in_sizes, int n_in,
                              void* d_out, int out_size) {
    const float* spec = (const float*)d_in[0];
    const float* W1   = (const float*)d_in[1];
    const float* b1   = (const float*)d_in[2];
    const float* W2   = (const float*)d_in[3];
    const float* b2   = (const float*)d_in[4];
    const float* R    = (const float*)d_in[5];
    float* out = (float*)d_out;

    compute_A_kernel<<<1, HID>>>(W2, R);
    solve_kernel<<<(BATCH * 2) / TPB, TPB>>>(spec, W1, b1, b2, R, out);
}

// round 7
// speedup vs baseline: 1.5501x; 1.5501x over previous
#include <cuda_runtime.h>

#define BATCH 16384
#define STEPS 200
#define LR 0.01f
#define HID 64
#define PROJ 8
#define SPEC 40
#define TPB 256

// Precomputed A = (W2 @ R^T) @ R[:, :6]  -> [HID][6]
__device__ float g_A[HID * 6];

// ---------------------------------------------------------------------------
// Prologue: A[k][i] = sum_p ( sum_j W2[k,j]*R[p,j] ) * R[p,i]
// ---------------------------------------------------------------------------
__global__ void compute_A_kernel(const float* __restrict__ W2,
                                 const float* __restrict__ R) {
    int k = threadIdx.x;
    if (k >= HID) return;
    float wr[PROJ];
#pragma unroll
    for (int p = 0; p < PROJ; p++) {
        float s = 0.f;
#pragma unroll
        for (int j = 0; j < SPEC; j++)
            s = fmaf(W2[k * SPEC + j], R[p * SPEC + j], s);
        wr[p] = s;
    }
#pragma unroll
    for (int i = 0; i < 6; i++) {
        float s = 0.f;
#pragma unroll
        for (int p = 0; p < PROJ; p++)
            s = fmaf(wr[p], R[p * SPEC + i], s);
        g_A[k * 6 + i] = s;
    }
}

// accurate tanh: 1 - 2/(exp(2x)+1); exp via MUFU.EX2, div via MUFU.RCP
// (~1e-7 abs err; identical math to the R3 kernel: rel_err 1.7e-7)
__device__ __forceinline__ float tanh_acc(float x) {
    float e;
    asm("ex2.approx.f32 %0, %1;" : "=f"(e) : "f"(2.885390081777927f * x));
    float r;
    asm("rcp.approx.f32 %0, %1;" : "=f"(r) : "f"(e + 1.f));
    return fmaf(-2.f, r, 1.f);
}

// ---------------------------------------------------------------------------
// Solver: TWO threads per row (lanes 2i, 2i+1 of one warp), split-K over the
// 64 hidden units (32 each). Scalar FMA body identical to the 461us R3 kernel;
// per-step cross-thread reduce = 6x shfl_xor(1) + 6 FADD (intra-warp, no BAR).
// Grid 128 x 256  ->  2 warps per SMSP on every SM (occupancy lever).
// ---------------------------------------------------------------------------
__global__ __launch_bounds__(TPB, 1)
void solve_kernel(const float* __restrict__ spec,
                  const float* __restrict__ W1,
                  const float* __restrict__ b1,
                  const float* __restrict__ b2,
                  const float* __restrict__ R,
                  float* __restrict__ out) {
    __shared__ float4 sW[HID][2];   // {w0..w3}, {w4,w5,b1,0}
    __shared__ float4 sA[HID][2];   // {a0..a3}, {a4,a5,0,0}
    __shared__ float  sR[PROJ * SPEC];
    __shared__ float  sB2[SPEC];

    const int tid = threadIdx.x;

    if (tid < HID) {
        int k = tid;
        sW[k][0] = make_float4(W1[0 * HID + k], W1[1 * HID + k],
                               W1[2 * HID + k], W1[3 * HID + k]);
        sW[k][1] = make_float4(W1[4 * HID + k], W1[5 * HID + k],
                               b1[k], 0.f);
        sA[k][0] = make_float4(g_A[k * 6 + 0], g_A[k * 6 + 1],
                               g_A[k * 6 + 2], g_A[k * 6 + 3]);
        sA[k][1] = make_float4(g_A[k * 6 + 4], g_A[k * 6 + 5], 0.f, 0.f);
    }
    for (int idx = tid; idx < PROJ * SPEC; idx += TPB) sR[idx] = R[idx];
    if (tid < SPEC) sB2[tid] = b2[tid];
    __syncthreads();

    const int gt   = blockIdx.x * TPB + tid;   // 0 .. 32767
    const int row  = gt >> 1;
    const int half = gt & 1;                   // which 32 hidden units
    const int kbeg = half * 32;

    // Per-row constant: c = R[:, :6]^T @ ( R @ (b2 - spec_row) )
    // (computed redundantly by both threads of a row — identical results)
    float z[PROJ];
#pragma unroll
    for (int p = 0; p < PROJ; p++) z[p] = 0.f;
    const float* srow = spec + (size_t)row * SPEC;
#pragma unroll 8
    for (int j = 0; j < SPEC; j++) {
        float d = sB2[j] - srow[j];
#pragma unroll
        for (int p = 0; p < PROJ; p++)
            z[p] = fmaf(sR[p * SPEC + j], d, z[p]);
    }
    float c0 = 0.f, c1 = 0.f, c2 = 0.f, c3 = 0.f, c4 = 0.f, c5 = 0.f;
#pragma unroll
    for (int p = 0; p < PROJ; p++) {
        c0 = fmaf(sR[p * SPEC + 0], z[p], c0);
        c1 = fmaf(sR[p * SPEC + 1], z[p], c1);
        c2 = fmaf(sR[p * SPEC + 2], z[p], c2);
        c3 = fmaf(sR[p * SPEC + 3], z[p], c3);
        c4 = fmaf(sR[p * SPEC + 4], z[p], c4);
        c5 = fmaf(sR[p * SPEC + 5], z[p], c5);
    }

    float u0 = 0.5f, u1 = 0.5f, u2 = 0.5f, u3 = 0.5f, u4 = 0.5f, u5 = 0.5f;

    for (int t = 0; t < STEPS; t++) {
        float g0 = 0.f, g1 = 0.f, g2 = 0.f, g3 = 0.f, g4 = 0.f, g5 = 0.f;
#pragma unroll 8
        for (int kk = 0; kk < 32; kk++) {
            const int k = kbeg + kk;
            const float4 wA = sW[k][0];
            const float4 wB = sW[k][1];
            float pre = wB.z;
            pre = fmaf(u0, wA.x, pre);
            pre = fmaf(u1, wA.y, pre);
            pre = fmaf(u2, wA.z, pre);
            pre = fmaf(u3, wA.w, pre);
            pre = fmaf(u4, wB.x, pre);
            pre = fmaf(u5, wB.y, pre);
            const float h = tanh_acc(pre);
            const float4 aA = sA[k][0];
            const float4 aB = sA[k][1];
            g0 = fmaf(h, aA.x, g0);
            g1 = fmaf(h, aA.y, g1);
            g2 = fmaf(h, aA.z, g2);
            g3 = fmaf(h, aA.w, g3);
            g4 = fmaf(h, aB.x, g4);
            g5 = fmaf(h, aB.y, g5);
        }
        // combine split-K partials across the lane pair (intra-warp)
        g0 += __shfl_xor_sync(0xffffffffu, g0, 1);
        g1 += __shfl_xor_sync(0xffffffffu, g1, 1);
        g2 += __shfl_xor_sync(0xffffffffu, g2, 1);
        g3 += __shfl_xor_sync(0xffffffffu, g3, 1);
        g4 += __shfl_xor_sync(0xffffffffu, g4, 1);
        g5 += __shfl_xor_sync(0xffffffffu, g5, 1);
        // u = clip(u - LR*(g + c), 0, 1)
        u0 = fminf(fmaxf(fmaf(-LR, g0, fmaf(-LR, c0, u0)), 0.f), 1.f);
        u1 = fminf(fmaxf(fmaf(-LR, g1, fmaf(-LR, c1, u1)), 0.f), 1.f);
        u2 = fminf(fmaxf(fmaf(-LR, g2, fmaf(-LR, c2, u2)), 0.f), 1.f);
        u3 = fminf(fmaxf(fmaf(-LR, g3, fmaf(-LR, c3, u3)), 0.f), 1.f);
        u4 = fminf(fmaxf(fmaf(-LR, g4, fmaf(-LR, c4, u4)), 0.f), 1.f);
        u5 = fminf(fmaxf(fmaf(-LR, g5, fmaf(-LR, c5, u5)), 0.f), 1.f);
    }

    if (half == 0) {
        float* orow = out + (size_t)row * 6;
        orow[0] = u0; orow[1] = u1; orow[2] = u2;
        orow[3] = u3; orow[4] = u4; orow[5] = u5;
    }
}

// ---------------------------------------------------------------------------
// Inputs (metadata order): spectrum, W1, b1, W2, b2, R.  Output: (BATCH, 6) f32
// ---------------------------------------------------------------------------
extern "C" void kernel_launch(void* const* d_in, const int* in_sizes, int n_in,
                              void* d_out, int out_size) {
    const float* spec = (const float*)d_in[0];
    const float* W1   = (const float*)d_in[1];
    const float* b1   = (const float*)d_in[2];
    const float* W2   = (const float*)d_in[3];
    const float* b2   = (const float*)d_in[4];
    const float* R    = (const float*)d_in[5];
    float* out = (float*)d_out;

    compute_A_kernel<<<1, HID>>>(W2, R);
    solve_kernel<<<(BATCH * 2) / TPB, TPB>>>(spec, W1, b1, b2, R, out);
}

// round 8
// speedup vs baseline: 2.3612x; 1.5232x over previous
#include <cuda_runtime.h>

#define BATCH 16384
#define STEPS 200
#define LR 0.01f
#define HID 64
#define PROJ 8
#define SPEC 40
#define TPB 256

// Precomputed A = (W2 @ R^T) @ R[:, :6]  -> [HID][6]
__device__ float g_A[HID * 6];

// ---------------------------------------------------------------------------
// Prologue: A[k][i] = sum_p ( sum_j W2[k,j]*R[p,j] ) * R[p,i]
// ---------------------------------------------------------------------------
__global__ void compute_A_kernel(const float* __restrict__ W2,
                                 const float* __restrict__ R) {
    int k = threadIdx.x;
    if (k >= HID) return;
    float wr[PROJ];
#pragma unroll
    for (int p = 0; p < PROJ; p++) {
        float s = 0.f;
#pragma unroll
        for (int j = 0; j < SPEC; j++)
            s = fmaf(W2[k * SPEC + j], R[p * SPEC + j], s);
        wr[p] = s;
    }
#pragma unroll
    for (int i = 0; i < 6; i++) {
        float s = 0.f;
#pragma unroll
        for (int p = 0; p < PROJ; p++)
            s = fmaf(wr[p], R[p * SPEC + i], s);
        g_A[k * 6 + i] = s;
    }
}

// accurate tanh: 1 - 2/(exp(2x)+1); exp via MUFU.EX2, div via MUFU.RCP
// (~1e-7 abs err; identical math to the R6 kernel: rel_err 2.3e-6)
__device__ __forceinline__ float tanh_acc(float x) {
    float e;
    asm("ex2.approx.f32 %0, %1;" : "=f"(e) : "f"(2.885390081777927f * x));
    float r;
    asm("rcp.approx.f32 %0, %1;" : "=f"(r) : "f"(e + 1.f));
    return fmaf(-2.f, r, 1.f);
}

// ---------------------------------------------------------------------------
// Solver: TWO threads per row (lanes 2i, 2i+1), split-K over the 64 hidden
// units (32 each). Identical instruction stream to the 367us R6 kernel.
//
// LAYOUT FIX vs R6: shared blocks are interleaved by half.
//   Hidden unit k = half*32 + kk lives at block index q = 2*kk + half.
// In R6, half-0/half-1 addresses differed by 1024B (same banks -> 2-way
// conflict on EVERY LDS.128 -> 2 wavefronts each, L1=82%). Interleaved, the
// two warp addresses differ by 32B (different banks) -> 1 wavefront.
// ---------------------------------------------------------------------------
__global__ __launch_bounds__(TPB, 1)
void solve_kernel(const float* __restrict__ spec,
                  const float* __restrict__ W1,
                  const float* __restrict__ b1,
                  const float* __restrict__ b2,
                  const float* __restrict__ R,
                  float* __restrict__ out) {
    __shared__ float4 sW[HID][2];   // block q: {w0..w3}, {w4,w5,b1,0}
    __shared__ float4 sA[HID][2];   // block q: {a0..a3}, {a4,a5,0,0}
    __shared__ float  sR[PROJ * SPEC];
    __shared__ float  sB2[SPEC];

    const int tid = threadIdx.x;

    if (tid < HID) {
        const int q = tid;              // block index
        const int h = q & 1;            // half
        const int kk = q >> 1;
        const int k = h * 32 + kk;      // hidden unit stored in this block
        sW[q][0] = make_float4(W1[0 * HID + k], W1[1 * HID + k],
                               W1[2 * HID + k], W1[3 * HID + k]);
        sW[q][1] = make_float4(W1[4 * HID + k], W1[5 * HID + k],
                               b1[k], 0.f);
        sA[q][0] = make_float4(g_A[k * 6 + 0], g_A[k * 6 + 1],
                               g_A[k * 6 + 2], g_A[k * 6 + 3]);
        sA[q][1] = make_float4(g_A[k * 6 + 4], g_A[k * 6 + 5], 0.f, 0.f);
    }
    for (int idx = tid; idx < PROJ * SPEC; idx += TPB) sR[idx] = R[idx];
    if (tid < SPEC) sB2[tid] = b2[tid];
    __syncthreads();

    const int gt   = blockIdx.x * TPB + tid;   // 0 .. 32767
    const int row  = gt >> 1;
    const int half = gt & 1;                   // which 32 hidden units

    // Per-row constant: c = R[:, :6]^T @ ( R @ (b2 - spec_row) )
    float z[PROJ];
#pragma unroll
    for (int p = 0; p < PROJ; p++) z[p] = 0.f;
    const float* srow = spec + (size_t)row * SPEC;
#pragma unroll 8
    for (int j = 0; j < SPEC; j++) {
        float d = sB2[j] - srow[j];
#pragma unroll
        for (int p = 0; p < PROJ; p++)
            z[p] = fmaf(sR[p * SPEC + j], d, z[p]);
    }
    float c0 = 0.f, c1 = 0.f, c2 = 0.f, c3 = 0.f, c4 = 0.f, c5 = 0.f;
#pragma unroll
    for (int p = 0; p < PROJ; p++) {
        c0 = fmaf(sR[p * SPEC + 0], z[p], c0);
        c1 = fmaf(sR[p * SPEC + 1], z[p], c1);
        c2 = fmaf(sR[p * SPEC + 2], z[p], c2);
        c3 = fmaf(sR[p * SPEC + 3], z[p], c3);
        c4 = fmaf(sR[p * SPEC + 4], z[p], c4);
        c5 = fmaf(sR[p * SPEC + 5], z[p], c5);
    }

    float u0 = 0.5f, u1 = 0.5f, u2 = 0.5f, u3 = 0.5f, u4 = 0.5f, u5 = 0.5f;

    for (int t = 0; t < STEPS; t++) {
        float g0 = 0.f, g1 = 0.f, g2 = 0.f, g3 = 0.f, g4 = 0.f, g5 = 0.f;
#pragma unroll 8
        for (int kk = 0; kk < 32; kk++) {
            const int q = (kk << 1) | half;    // interleaved block index
            const float4 wA = sW[q][0];
            const float4 wB = sW[q][1];
            float pre = wB.z;
            pre = fmaf(u0, wA.x, pre);
            pre = fmaf(u1, wA.y, pre);
            pre = fmaf(u2, wA.z, pre);
            pre = fmaf(u3, wA.w, pre);
            pre = fmaf(u4, wB.x, pre);
            pre = fmaf(u5, wB.y, pre);
            const float h = tanh_acc(pre);
            const float4 aA = sA[q][0];
            const float4 aB = sA[q][1];
            g0 = fmaf(h, aA.x, g0);
            g1 = fmaf(h, aA.y, g1);
            g2 = fmaf(h, aA.z, g2);
            g3 = fmaf(h, aA.w, g3);
            g4 = fmaf(h, aB.x, g4);
            g5 = fmaf(h, aB.y, g5);
        }
        // combine split-K partials across the lane pair (intra-warp)
        g0 += __shfl_xor_sync(0xffffffffu, g0, 1);
        g1 += __shfl_xor_sync(0xffffffffu, g1, 1);
        g2 += __shfl_xor_sync(0xffffffffu, g2, 1);
        g3 += __shfl_xor_sync(0xffffffffu, g3, 1);
        g4 += __shfl_xor_sync(0xffffffffu, g4, 1);
        g5 += __shfl_xor_sync(0xffffffffu, g5, 1);
        // u = clip(u - LR*(g + c), 0, 1)
        u0 = fminf(fmaxf(fmaf(-LR, g0, fmaf(-LR, c0, u0)), 0.f), 1.f);
        u1 = fminf(fmaxf(fmaf(-LR, g1, fmaf(-LR, c1, u1)), 0.f), 1.f);
        u2 = fminf(fmaxf(fmaf(-LR, g2, fmaf(-LR, c2, u2)), 0.f), 1.f);
        u3 = fminf(fmaxf(fmaf(-LR, g3, fmaf(-LR, c3, u3)), 0.f), 1.f);
        u4 = fminf(fmaxf(fmaf(-LR, g4, fmaf(-LR, c4, u4)), 0.f), 1.f);
        u5 = fminf(fmaxf(fmaf(-LR, g5, fmaf(-LR, c5, u5)), 0.f), 1.f);
    }

    if (half == 0) {
        float* orow = out + (size_t)row * 6;
        orow[0] = u0; orow[1] = u1; orow[2] = u2;
        orow[3] = u3; orow[4] = u4; orow[5] = u5;
    }
}

// ---------------------------------------------------------------------------
// Inputs (metadata order): spectrum, W1, b1, W2, b2, R.  Output: (BATCH, 6) f32
// ---------------------------------------------------------------------------
extern "C" void kernel_launch(void* const* d_in, const int* in_sizes, int n_in,
                              void* d_out, int out_size) {
    const float* spec = (const float*)d_in[0];
    const float* W1   = (const float*)d_in[1];
    const float* b1   = (const float*)d_in[2];
    const float* W2   = (const float*)d_in[3];
    const float* b2   = (const float*)d_in[4];
    const float* R    = (const float*)d_in[5];
    float* out = (float*)d_out;

    compute_A_kernel<<<1, HID>>>(W2, R);
    solve_kernel<<<(BATCH * 2) / TPB, TPB>>>(spec, W1, b1, b2, R, out);
}

// round 9
// speedup vs baseline: 3.0758x; 1.3027x over previous
#include <cuda_runtime.h>

#define BATCH 16384
#define STEPS 200
#define LR 0.01f
#define HID 64
#define PROJ 8
#define SPEC 40
#define TPB 256

typedef unsigned long long ull;

// Precomputed A = (W2 @ R^T) @ R[:, :6]  -> [HID][6]
__device__ float g_A[HID * 6];

__global__ void compute_A_kernel(const float* __restrict__ W2,
                                 const float* __restrict__ R) {
    int k = threadIdx.x;
    if (k >= HID) return;
    float wr[PROJ];
#pragma unroll
    for (int p = 0; p < PROJ; p++) {
        float s = 0.f;
#pragma unroll
        for (int j = 0; j < SPEC; j++)
            s = fmaf(W2[k * SPEC + j], R[p * SPEC + j], s);
        wr[p] = s;
    }
#pragma unroll
    for (int i = 0; i < 6; i++) {
        float s = 0.f;
#pragma unroll
        for (int p = 0; p < PROJ; p++)
            s = fmaf(wr[p], R[p * SPEC + i], s);
        g_A[k * 6 + i] = s;
    }
}

// ---- packed f32x2 / misc helpers -------------------------------------------
__device__ __forceinline__ ull fma2(ull a, ull b, ull c) {
    ull r;
    asm("fma.rn.f32x2 %0, %1, %2, %3;" : "=l"(r) : "l"(a), "l"(b), "l"(c));
    return r;
}
__device__ __forceinline__ ull pk(float lo, float hi) {
    ull r;
    asm("mov.b64 %0, {%1, %2};" : "=l"(r) : "f"(lo), "f"(hi));
    return r;
}
__device__ __forceinline__ void upk(ull v, float& lo, float& hi) {
    asm("mov.b64 {%0, %1}, %2;" : "=f"(lo), "=f"(hi) : "l"(v));
}
__device__ __forceinline__ ull pkc(float lo, float hi) {
    return (ull)__float_as_uint(lo) | ((ull)__float_as_uint(hi) << 32);
}
__device__ __forceinline__ float tanh_fast(float x) {
    float r;
    asm("tanh.approx.f32 %0, %1;" : "=f"(r) : "f"(x));
    return r;
}

// ---------------------------------------------------------------------------
// Solver: TWO threads per row (lanes 2i, 2i+1), split-K over 64 hidden units
// (32 each), processed as 16 packed (k,k+1) pairs with fma.rn.f32x2 and
// tanh.approx.f32.
//
// Shared layout: TWO arrays, 64B-stride blocks, block index q = pair*2 + half
// (pair = 0..15 inside a thread, half = thread's split-K side):
//   sWp[q*8 + {0..5}] = {W1[i][k0], W1[i][k1]} packed   (i = 0..5)
//   sWp[q*8 + 6]      = {b1[k0], b1[k1]},  [7] = pad
//   sAp[q*8 + {0..5}] = {A[k0][j], A[k1][j]} packed     (j = 0..5)
// with k0 = half*32 + pair*2, k1 = k0+1.
// Bank check: half-0 blocks at byte 0 mod 128 (banks 0-15), half-1 at byte 64
// mod 128 (banks 16-31) -> the warp's two broadcast addresses never collide.
// ---------------------------------------------------------------------------
__global__ __launch_bounds__(TPB, 1)
void solve_kernel(const float* __restrict__ spec,
                  const float* __restrict__ W1,
                  const float* __restrict__ b1,
                  const float* __restrict__ b2,
                  const float* __restrict__ R,
                  float* __restrict__ out) {
    __shared__ ull sWp[32 * 8];     // 2048 B
    __shared__ ull sAp[32 * 8];     // 2048 B
    __shared__ float sR[PROJ * SPEC];
    __shared__ float sB2[SPEC];

    const int tid = threadIdx.x;

    if (tid < 32) {
        const int q = tid, h = q & 1, pair = q >> 1;
        const int k0 = h * 32 + pair * 2, k1 = k0 + 1;
#pragma unroll
        for (int i = 0; i < 6; i++)
            sWp[q * 8 + i] = pkc(W1[i * HID + k0], W1[i * HID + k1]);
        sWp[q * 8 + 6] = pkc(b1[k0], b1[k1]);
        sWp[q * 8 + 7] = 0ULL;
#pragma unroll
        for (int j = 0; j < 6; j++)
            sAp[q * 8 + j] = pkc(g_A[k0 * 6 + j], g_A[k1 * 6 + j]);
        sAp[q * 8 + 6] = 0ULL;
        sAp[q * 8 + 7] = 0ULL;
    }
    for (int idx = tid; idx < PROJ * SPEC; idx += TPB) sR[idx] = R[idx];
    if (tid < SPEC) sB2[tid] = b2[tid];
    __syncthreads();

    const int gt   = blockIdx.x * TPB + tid;   // 0 .. 32767
    const int row  = gt >> 1;
    const int half = gt & 1;
    const ulonglong2* wbase = (const ulonglong2*)(sWp + half * 8);
    const ulonglong2* abase = (const ulonglong2*)(sAp + half * 8);

    // Per-row constant: c = R[:, :6]^T @ ( R @ (b2 - spec_row) )
    float z[PROJ];
#pragma unroll
    for (int p = 0; p < PROJ; p++) z[p] = 0.f;
    const float* srow = spec + (size_t)row * SPEC;
#pragma unroll 8
    for (int j = 0; j < SPEC; j++) {
        float d = sB2[j] - srow[j];
#pragma unroll
        for (int p = 0; p < PROJ; p++)
            z[p] = fmaf(sR[p * SPEC + j], d, z[p]);
    }
    float c0 = 0.f, c1 = 0.f, c2 = 0.f, c3 = 0.f, c4 = 0.f, c5 = 0.f;
#pragma unroll
    for (int p = 0; p < PROJ; p++) {
        c0 = fmaf(sR[p * SPEC + 0], z[p], c0);
        c1 = fmaf(sR[p * SPEC + 1], z[p], c1);
        c2 = fmaf(sR[p * SPEC + 2], z[p], c2);
        c3 = fmaf(sR[p * SPEC + 3], z[p], c3);
        c4 = fmaf(sR[p * SPEC + 4], z[p], c4);
        c5 = fmaf(sR[p * SPEC + 5], z[p], c5);
    }

    float u0 = 0.5f, u1 = 0.5f, u2 = 0.5f, u3 = 0.5f, u4 = 0.5f, u5 = 0.5f;

    for (int t = 0; t < STEPS; t++) {
        const ull pu0 = pk(u0, u0), pu1 = pk(u1, u1), pu2 = pk(u2, u2),
                  pu3 = pk(u3, u3), pu4 = pk(u4, u4), pu5 = pk(u5, u5);
        ull G0 = 0ULL, G1 = 0ULL, G2 = 0ULL, G3 = 0ULL, G4 = 0ULL, G5 = 0ULL;
#pragma unroll 4
        for (int p = 0; p < 16; p++) {
            // block q = p*2 + half  ->  (ulonglong2 units) base + p*8
            const ulonglong2 w01 = wbase[p * 8 + 0];
            const ulonglong2 w23 = wbase[p * 8 + 1];
            const ulonglong2 w45 = wbase[p * 8 + 2];
            const ulonglong2 wb_ = wbase[p * 8 + 3];   // {b, pad}
            ull pre2 = wb_.x;
            pre2 = fma2(pu0, w01.x, pre2);
            pre2 = fma2(pu1, w01.y, pre2);
            pre2 = fma2(pu2, w23.x, pre2);
            pre2 = fma2(pu3, w23.y, pre2);
            pre2 = fma2(pu4, w45.x, pre2);
            pre2 = fma2(pu5, w45.y, pre2);
            float x0, x1;
            upk(pre2, x0, x1);
            const ull h2 = pk(tanh_fast(x0), tanh_fast(x1));
            const ulonglong2 a01 = abase[p * 8 + 0];
            const ulonglong2 a23 = abase[p * 8 + 1];
            const ulonglong2 a45 = abase[p * 8 + 2];
            G0 = fma2(h2, a01.x, G0);
            G1 = fma2(h2, a01.y, G1);
            G2 = fma2(h2, a23.x, G2);
            G3 = fma2(h2, a23.y, G3);
            G4 = fma2(h2, a45.x, G4);
            G5 = fma2(h2, a45.y, G5);
        }
        // fold packed lanes, then reduce across the 2 split-K threads
        float a, b, g0, g1, g2, g3, g4, g5;
        upk(G0, a, b); g0 = a + b;
        upk(G1, a, b); g1 = a + b;
        upk(G2, a, b); g2 = a + b;
        upk(G3, a, b); g3 = a + b;
        upk(G4, a, b); g4 = a + b;
        upk(G5, a, b); g5 = a + b;
        g0 += __shfl_xor_sync(0xffffffffu, g0, 1);
        g1 += __shfl_xor_sync(0xffffffffu, g1, 1);
        g2 += __shfl_xor_sync(0xffffffffu, g2, 1);
        g3 += __shfl_xor_sync(0xffffffffu, g3, 1);
        g4 += __shfl_xor_sync(0xffffffffu, g4, 1);
        g5 += __shfl_xor_sync(0xffffffffu, g5, 1);
        // u = clip(u - LR*(g + c), 0, 1)
        u0 = fminf(fmaxf(fmaf(-LR, g0, fmaf(-LR, c0, u0)), 0.f), 1.f);
        u1 = fminf(fmaxf(fmaf(-LR, g1, fmaf(-LR, c1, u1)), 0.f), 1.f);
        u2 = fminf(fmaxf(fmaf(-LR, g2, fmaf(-LR, c2, u2)), 0.f), 1.f);
        u3 = fminf(fmaxf(fmaf(-LR, g3, fmaf(-LR, c3, u3)), 0.f), 1.f);
        u4 = fminf(fmaxf(fmaf(-LR, g4, fmaf(-LR, c4, u4)), 0.f), 1.f);
        u5 = fminf(fmaxf(fmaf(-LR, g5, fmaf(-LR, c5, u5)), 0.f), 1.f);
    }

    if (half == 0) {
        float* orow = out + (size_t)row * 6;
        orow[0] = u0; orow[1] = u1; orow[2] = u2;
        orow[3] = u3; orow[4] = u4; orow[5] = u5;
    }
}

// ---------------------------------------------------------------------------
// Inputs (metadata order): spectrum, W1, b1, W2, b2, R.  Output: (BATCH, 6) f32
// ---------------------------------------------------------------------------
extern "C" void kernel_launch(void* const* d_in, const int* in_sizes, int n_in,
                              void* d_out, int out_size) {
    const float* spec = (const float*)d_in[0];
    const float* W1   = (const float*)d_in[1];
    const float* b1   = (const float*)d_in[2];
    const float* W2   = (const float*)d_in[3];
    const float* b2   = (const float*)d_in[4];
    const float* R    = (const float*)d_in[5];
    float* out = (float*)d_out;

    compute_A_kernel<<<1, HID>>>(W2, R);
    solve_kernel<<<(BATCH * 2) / TPB, TPB>>>(spec, W1, b1, b2, R, out);
}

// round 10
// speedup vs baseline: 3.7309x; 1.2130x over previous
#include <cuda_runtime.h>

#define BATCH 16384
#define STEPS 200
#define LR 0.01f
#define HID 64
#define PROJ 8
#define SPEC 40
#define TPB 128

typedef unsigned long long ull;

// Precomputed A = (W2 @ R^T) @ R[:, :6]  -> [HID][6]
__device__ float g_A[HID * 6];

__global__ void compute_A_kernel(const float* __restrict__ W2,
                                 const float* __restrict__ R) {
    int k = threadIdx.x;
    if (k >= HID) return;
    float wr[PROJ];
#pragma unroll
    for (int p = 0; p < PROJ; p++) {
        float s = 0.f;
#pragma unroll
        for (int j = 0; j < SPEC; j++)
            s = fmaf(W2[k * SPEC + j], R[p * SPEC + j], s);
        wr[p] = s;
    }
#pragma unroll
    for (int i = 0; i < 6; i++) {
        float s = 0.f;
#pragma unroll
        for (int p = 0; p < PROJ; p++)
            s = fmaf(wr[p], R[p * SPEC + i], s);
        g_A[k * 6 + i] = s;
    }
}

// ---- packed f32x2 / misc helpers -------------------------------------------
__device__ __forceinline__ ull fma2(ull a, ull b, ull c) {
    ull r;
    asm("fma.rn.f32x2 %0, %1, %2, %3;" : "=l"(r) : "l"(a), "l"(b), "l"(c));
    return r;
}
__device__ __forceinline__ ull pk(float lo, float hi) {
    ull r;
    asm("mov.b64 %0, {%1, %2};" : "=l"(r) : "f"(lo), "f"(hi));
    return r;
}
__device__ __forceinline__ void upk(ull v, float& lo, float& hi) {
    asm("mov.b64 {%0, %1}, %2;" : "=f"(lo), "=f"(hi) : "l"(v));
}
__device__ __forceinline__ ull pkc(float lo, float hi) {
    return (ull)__float_as_uint(lo) | ((ull)__float_as_uint(hi) << 32);
}
__device__ __forceinline__ float tanh_fast(float x) {
    float r;
    asm("tanh.approx.f32 %0, %1;" : "=f"(r) : "f"(x));
    return r;
}

// ---------------------------------------------------------------------------
// Solver: each thread handles TWO rows (rA, rB) and HALF the hidden units
// (split-K(2) across lane pairs 2i/2i+1), pairs packed with fma.rn.f32x2.
// The 112B/pair weight stream from shared is loaded ONCE and feeds BOTH rows
// -> LDS wavefronts per SM halved vs R8 while fma2 work per warp doubles.
//
// Shared layout identical to R8 (proven conflict-free): blocks of 8 ull,
// block index q = pair*2 + half;  half-0 at 0 mod 128B (banks 0-15),
// half-1 at 64 mod 128B (banks 16-31).
// ---------------------------------------------------------------------------
__global__ __launch_bounds__(TPB, 1)
void solve_kernel(const float* __restrict__ spec,
                  const float* __restrict__ W1,
                  const float* __restrict__ b1,
                  const float* __restrict__ b2,
                  const float* __restrict__ R,
                  float* __restrict__ out) {
    __shared__ ull sWp[32 * 8];     // 2048 B
    __shared__ ull sAp[32 * 8];     // 2048 B
    __shared__ float sR[PROJ * SPEC];
    __shared__ float sB2[SPEC];

    const int tid = threadIdx.x;

    if (tid < 32) {
        const int q = tid, h = q & 1, pair = q >> 1;
        const int k0 = h * 32 + pair * 2, k1 = k0 + 1;
#pragma unroll
        for (int i = 0; i < 6; i++)
            sWp[q * 8 + i] = pkc(W1[i * HID + k0], W1[i * HID + k1]);
        sWp[q * 8 + 6] = pkc(b1[k0], b1[k1]);
        sWp[q * 8 + 7] = 0ULL;
#pragma unroll
        for (int j = 0; j < 6; j++)
            sAp[q * 8 + j] = pkc(g_A[k0 * 6 + j], g_A[k1 * 6 + j]);
        sAp[q * 8 + 6] = 0ULL;
        sAp[q * 8 + 7] = 0ULL;
    }
    for (int idx = tid; idx < PROJ * SPEC; idx += TPB) sR[idx] = R[idx];
    if (tid < SPEC) sB2[tid] = b2[tid];
    __syncthreads();

    const int gt   = blockIdx.x * TPB + tid;   // 0 .. 16383
    const int rp   = gt >> 1;                  // row-pair index 0..8191
    const int half = gt & 1;
    const int rA   = rp * 2, rB = rA + 1;
    const ulonglong2* wbase = (const ulonglong2*)(sWp + half * 8);
    const ulonglong2* abase = (const ulonglong2*)(sAp + half * 8);

    // Per-row constants c[6] for both rows: c = R[:, :6]^T @ ( R @ (b2-spec) )
    float cA[6], cB[6];
#pragma unroll
    for (int r = 0; r < 2; r++) {
        const float* srow = spec + (size_t)(rA + r) * SPEC;
        float z[PROJ];
#pragma unroll
        for (int p = 0; p < PROJ; p++) z[p] = 0.f;
#pragma unroll 8
        for (int j = 0; j < SPEC; j++) {
            float d = sB2[j] - srow[j];
#pragma unroll
            for (int p = 0; p < PROJ; p++)
                z[p] = fmaf(sR[p * SPEC + j], d, z[p]);
        }
        float* c = r ? cB : cA;
#pragma unroll
        for (int i = 0; i < 6; i++) {
            float s = 0.f;
#pragma unroll
            for (int p = 0; p < PROJ; p++)
                s = fmaf(sR[p * SPEC + i], z[p], s);
            c[i] = s;
        }
    }

    float uA[6], uB[6];
#pragma unroll
    for (int i = 0; i < 6; i++) { uA[i] = 0.5f; uB[i] = 0.5f; }

    for (int t = 0; t < STEPS; t++) {
        ull puA[6], puB[6];
#pragma unroll
        for (int i = 0; i < 6; i++) {
            puA[i] = pk(uA[i], uA[i]);
            puB[i] = pk(uB[i], uB[i]);
        }
        ull GA[6], GB[6];
#pragma unroll
        for (int i = 0; i < 6; i++) { GA[i] = 0ULL; GB[i] = 0ULL; }

#pragma unroll 4
        for (int p = 0; p < 16; p++) {
            const ulonglong2 w01 = wbase[p * 8 + 0];
            const ulonglong2 w23 = wbase[p * 8 + 1];
            const ulonglong2 w45 = wbase[p * 8 + 2];
            const ulonglong2 wb_ = wbase[p * 8 + 3];   // {b, pad}
            // two independent pre-chains (rows A and B) — ILP
            ull preA = wb_.x, preB = wb_.x;
            preA = fma2(puA[0], w01.x, preA);  preB = fma2(puB[0], w01.x, preB);
            preA = fma2(puA[1], w01.y, preA);  preB = fma2(puB[1], w01.y, preB);
            preA = fma2(puA[2], w23.x, preA);  preB = fma2(puB[2], w23.x, preB);
            preA = fma2(puA[3], w23.y, preA);  preB = fma2(puB[3], w23.y, preB);
            preA = fma2(puA[4], w45.x, preA);  preB = fma2(puB[4], w45.x, preB);
            preA = fma2(puA[5], w45.y, preA);  preB = fma2(puB[5], w45.y, preB);
            float xa0, xa1, xb0, xb1;
            upk(preA, xa0, xa1);
            upk(preB, xb0, xb1);
            const ull hA = pk(tanh_fast(xa0), tanh_fast(xa1));
            const ull hB = pk(tanh_fast(xb0), tanh_fast(xb1));
            const ulonglong2 a01 = abase[p * 8 + 0];
            const ulonglong2 a23 = abase[p * 8 + 1];
            const ulonglong2 a45 = abase[p * 8 + 2];
            GA[0] = fma2(hA, a01.x, GA[0]);  GB[0] = fma2(hB, a01.x, GB[0]);
            GA[1] = fma2(hA, a01.y, GA[1]);  GB[1] = fma2(hB, a01.y, GB[1]);
            GA[2] = fma2(hA, a23.x, GA[2]);  GB[2] = fma2(hB, a23.x, GB[2]);
            GA[3] = fma2(hA, a23.y, GA[3]);  GB[3] = fma2(hB, a23.y, GB[3]);
            GA[4] = fma2(hA, a45.x, GA[4]);  GB[4] = fma2(hB, a45.x, GB[4]);
            GA[5] = fma2(hA, a45.y, GA[5]);  GB[5] = fma2(hB, a45.y, GB[5]);
        }
        // fold packed lanes, reduce across the split-K lane pair, update u
#pragma unroll
        for (int i = 0; i < 6; i++) {
            float a, b;
            upk(GA[i], a, b);
            float g = a + b;
            g += __shfl_xor_sync(0xffffffffu, g, 1);
            uA[i] = fminf(fmaxf(fmaf(-LR, g, fmaf(-LR, cA[i], uA[i])), 0.f), 1.f);
        }
#pragma unroll
        for (int i = 0; i < 6; i++) {
            float a, b;
            upk(GB[i], a, b);
            float g = a + b;
            g += __shfl_xor_sync(0xffffffffu, g, 1);
            uB[i] = fminf(fmaxf(fmaf(-LR, g, fmaf(-LR, cB[i], uB[i])), 0.f), 1.f);
        }
    }

    if (half == 0) {
        float* oA = out + (size_t)rA * 6;
        float* oB = out + (size_t)rB * 6;
#pragma unroll
        for (int i = 0; i < 6; i++) { oA[i] = uA[i]; oB[i] = uB[i]; }
    }
}

// ---------------------------------------------------------------------------
// Inputs (metadata order): spectrum, W1, b1, W2, b2, R.  Output: (BATCH, 6) f32
// ---------------------------------------------------------------------------
extern "C" void kernel_launch(void* const* d_in, const int* in_sizes, int n_in,
                              void* d_out, int out_size) {
    const float* spec = (const float*)d_in[0];
    const float* W1   = (const float*)d_in[1];
    const float* b1   = (const float*)d_in[2];
    const float* W2   = (const float*)d_in[3];
    const float* b2   = (const float*)d_in[4];
    const float* R    = (const float*)d_in[5];
    float* out = (float*)d_out;

    compute_A_kernel<<<1, HID>>>(W2, R);
    solve_kernel<<<BATCH / TPB, TPB>>>(spec, W1, b1, b2, R, out);
}